// round 6
// baseline (speedup 1.0000x reference)
#include <cuda_runtime.h>

// NSLayer: out = X + (w0*A + ... + w6*A^7 + w7*I) @ X,  A = I - X X^T
// 262144 independent 8x8 fp32 matrices. FOUR threads per matrix (column
// split: thread h owns columns 2h,2h+1). Power iterations Y <- A*Y are
// column-local -> no communication; the Gram matrix needs a 2-hop shfl.bfly
// reduction within the owning quad. All math in packed fma.rn.f32x2 (FFMA2).
// Register budget ~125 -> 4 CTAs/SM (16 warps) for issue-slot occupancy.

static constexpr int MPB = 32;    // matrices per block
static constexpr int TPB = 128;   // threads per block (4 per matrix)
static constexpr int PL4 = 66;    // smem plane stride in float4 (64 + pad 2)

typedef unsigned long long u64;

__device__ __forceinline__ u64 pack2(float lo, float hi) {
    u64 r; asm("mov.b64 %0, {%1, %2};" : "=l"(r) : "f"(lo), "f"(hi)); return r;
}
__device__ __forceinline__ void unpack2(u64 v, float& lo, float& hi) {
    asm("mov.b64 {%0, %1}, %2;" : "=f"(lo), "=f"(hi) : "l"(v));
}
__device__ __forceinline__ u64 fma2(u64 a, u64 b, u64 c) {
    u64 d; asm("fma.rn.f32x2 %0, %1, %2, %3;" : "=l"(d) : "l"(a), "l"(b), "l"(c)); return d;
}
__device__ __forceinline__ u64 mul2(u64 a, u64 b) {
    u64 d; asm("mul.rn.f32x2 %0, %1, %2;" : "=l"(d) : "l"(a), "l"(b)); return d;
}

#define TRI(r, k) ((r) >= (k) ? ((r) * ((r) + 1) / 2 + (k)) : ((k) * ((k) + 1) / 2 + (r)))

__global__ __launch_bounds__(TPB, 4)
void nslayer_kernel(const float* __restrict__ x,
                    const float* __restrict__ weight,
                    float* __restrict__ out)
{
    // Plane r: 32 matrices x 2 float4 (row r of each matrix). As 8B units,
    // thread t's pair of columns of row r lives at unit r*132 + t ->
    // consecutive lanes hit consecutive 8B units: conflict-free LDS/STS.64.
    __shared__ float4 s4[8 * PL4];
    u64* su = reinterpret_cast<u64*>(s4);
    const int tid = threadIdx.x;
    const size_t base4 = (size_t)blockIdx.x * (MPB * 16);

    // ---- coalesced load: block's 8KB chunk -> planar smem ----
    const float4* gin = reinterpret_cast<const float4*>(x) + base4;
#pragma unroll
    for (int k = 0; k < 4; k++) {
        int l4 = tid + k * TPB;
        int m = l4 >> 4, r = (l4 >> 1) & 7, q = l4 & 1;
        s4[r * PL4 + m * 2 + q] = gin[l4];
    }
    __syncthreads();

    // ---- my slice: all 8 rows x my 2 columns, one packed pair per row ----
    u64 Y2[8];
#pragma unroll
    for (int r = 0; r < 8; r++) Y2[r] = su[r * (PL4 * 2) + tid];

    // ---- A = I - Y Y^T : partial dot over my 2 cols, quad bfly reduce ----
    u64 A2[36];
#pragma unroll
    for (int r = 0; r < 8; r++) {
#pragma unroll
        for (int c = 0; c <= r; c++) {
            u64 d2 = mul2(Y2[r], Y2[c]);
            float lo, hi; unpack2(d2, lo, hi);
            float p = lo + hi;
            p += __shfl_xor_sync(0xffffffffu, p, 1);
            p += __shfl_xor_sync(0xffffffffu, p, 2);
            float v = ((r == c) ? 1.0f : 0.0f) - p;
            A2[TRI(r, c)] = pack2(v, v);
        }
    }

    // ---- Acc = (w7 + 1) * X  (my columns) ----
    const float w7p1 = __ldg(&weight[7]) + 1.0f;
    const u64 w7p1x2 = pack2(w7p1, w7p1);
    u64 Acc2[8];
#pragma unroll
    for (int r = 0; r < 8; r++) Acc2[r] = mul2(w7p1x2, Y2[r]);

    // ---- Y <- A*Y seven times (column-local, no comm); Acc += w[i]*Y ----
    for (int i = 0; i < 7; i++) {
        const float wi = __ldg(&weight[i]);
        const u64 wi2 = pack2(wi, wi);
        u64 t2[8];
#pragma unroll
        for (int r = 0; r < 8; r++) {
            u64 d2 = mul2(A2[TRI(r, 0)], Y2[0]);
#pragma unroll
            for (int k = 1; k < 8; k++)
                d2 = fma2(A2[TRI(r, k)], Y2[k], d2);
            t2[r] = d2;
        }
#pragma unroll
        for (int r = 0; r < 8; r++) {
            Y2[r] = t2[r];
            Acc2[r] = fma2(wi2, t2[r], Acc2[r]);
        }
    }

    // ---- write my slice back (self-owned slots, conflict-free STS.64) ----
#pragma unroll
    for (int r = 0; r < 8; r++) su[r * (PL4 * 2) + tid] = Acc2[r];
    __syncthreads();

    // ---- coalesced store: planar smem -> block's output chunk ----
    float4* gout = reinterpret_cast<float4*>(out) + base4;
#pragma unroll
    for (int k = 0; k < 4; k++) {
        int l4 = tid + k * TPB;
        int m = l4 >> 4, r = (l4 >> 1) & 7, q = l4 & 1;
        gout[l4] = s4[r * PL4 + m * 2 + q];
    }
}

extern "C" void kernel_launch(void* const* d_in, const int* in_sizes, int n_in,
                              void* d_out, int out_size) {
    const float* x = (const float*)d_in[0];
    const float* w = (const float*)d_in[1];
    float* out = (float*)d_out;
    int nmat = in_sizes[0] / 64;          // 262144
    int blocks = nmat / MPB;              // 8192 (exact)
    nslayer_kernel<<<blocks, TPB>>>(x, w, out);
}

// round 7
// speedup vs baseline: 1.0770x; 1.0770x over previous
#include <cuda_runtime.h>

// NSLayer: out = X + (w0*A + ... + w6*A^7 + w7*I) @ X,  A = I - X X^T
// 262144 independent 8x8 fp32 matrices. TWO threads per matrix (column split:
// thread h owns columns 4h..4h+3). Power iterations Y <- A*Y are column-local
// -> no communication; only the Gram matrix needs one 36-value shfl.bfly
// reduction. All math in packed fma.rn.f32x2 (SASS FFMA2).
// R5: power loop FULLY UNROLLED (kills per-iter t->Y register MOVs and the
// in-loop weight LDG); weights preloaded via two float4 loads.

static constexpr int MPB = 64;    // matrices per block
static constexpr int TPB = 128;   // threads per block (2 per matrix)
static constexpr int PL  = 130;   // smem plane stride in float4 (pad 128->130)

typedef unsigned long long u64;

__device__ __forceinline__ u64 pack2(float lo, float hi) {
    u64 r; asm("mov.b64 %0, {%1, %2};" : "=l"(r) : "f"(lo), "f"(hi)); return r;
}
__device__ __forceinline__ void unpack2(u64 v, float& lo, float& hi) {
    asm("mov.b64 {%0, %1}, %2;" : "=f"(lo), "=f"(hi) : "l"(v));
}
__device__ __forceinline__ u64 fma2(u64 a, u64 b, u64 c) {
    u64 d; asm("fma.rn.f32x2 %0, %1, %2, %3;" : "=l"(d) : "l"(a), "l"(b), "l"(c)); return d;
}
__device__ __forceinline__ u64 mul2(u64 a, u64 b) {
    u64 d; asm("mul.rn.f32x2 %0, %1, %2;" : "=l"(d) : "l"(a), "l"(b)); return d;
}

#define TRI(r, k) ((r) >= (k) ? ((r) * ((r) + 1) / 2 + (k)) : ((k) * ((k) + 1) / 2 + (r)))

__global__ __launch_bounds__(TPB, 3)
void nslayer_kernel(const float* __restrict__ x,
                    const float* __restrict__ weight,
                    float* __restrict__ out)
{
    // Plane r holds, at float4 slot (m*2+h), row r cols 4h..4h+3 of matrix m.
    __shared__ float4 s4[8 * PL];
    const int tid = threadIdx.x;
    const size_t base4 = (size_t)blockIdx.x * (MPB * 16);

    // ---- preload weights (two coalesced float4 LDGs, broadcast via L1) ----
    const float4 wA = __ldg(reinterpret_cast<const float4*>(weight));
    const float4 wB = __ldg(reinterpret_cast<const float4*>(weight) + 1);
    const float wv[8] = { wA.x, wA.y, wA.z, wA.w, wB.x, wB.y, wB.z, wB.w };

    // ---- coalesced load: block's 16KB chunk -> planar smem ----
    const float4* gin = reinterpret_cast<const float4*>(x) + base4;
#pragma unroll
    for (int k = 0; k < 8; k++) {
        int l4 = tid + k * TPB;
        int m = l4 >> 4, r = (l4 >> 1) & 7, q = l4 & 1;
        s4[r * PL + m * 2 + q] = gin[l4];
    }
    __syncthreads();

    // ---- my half: all 8 rows x my 4 columns, 2 packed pairs per row ----
    u64 Y2[8][2];
#pragma unroll
    for (int r = 0; r < 8; r++) {
        ulonglong2 p = *reinterpret_cast<const ulonglong2*>(&s4[r * PL + tid]);
        Y2[r][0] = p.x; Y2[r][1] = p.y;
    }

    // ---- A = I - Y Y^T : partial dot over my 4 cols, bfly reduce with
    //      partner lane (tid^1), broadcast-pack lower triangle ----
    u64 A2[36];
#pragma unroll
    for (int r = 0; r < 8; r++) {
#pragma unroll
        for (int c = 0; c <= r; c++) {
            u64 d2 = mul2(Y2[r][0], Y2[c][0]);
            d2 = fma2(Y2[r][1], Y2[c][1], d2);
            float lo, hi; unpack2(d2, lo, hi);
            float p = lo + hi;
            p += __shfl_xor_sync(0xffffffffu, p, 1);
            float v = ((r == c) ? 1.0f : 0.0f) - p;
            A2[TRI(r, c)] = pack2(v, v);
        }
    }

    // ---- Acc = (w7 + 1) * X  (my columns) ----
    const float w7p1 = wv[7] + 1.0f;
    const u64 w7p1x2 = pack2(w7p1, w7p1);
    u64 Acc2[8][2];
#pragma unroll
    for (int r = 0; r < 8; r++) {
        Acc2[r][0] = mul2(w7p1x2, Y2[r][0]);
        Acc2[r][1] = mul2(w7p1x2, Y2[r][1]);
    }

    // ---- Y <- A*Y seven times (FULLY UNROLLED); Acc += w[i]*Y ----
#pragma unroll
    for (int i = 0; i < 7; i++) {
        const u64 wi2 = pack2(wv[i], wv[i]);
#pragma unroll
        for (int cp = 0; cp < 2; cp++) {
            u64 t2[8];
#pragma unroll
            for (int r = 0; r < 8; r++) {
                u64 d2 = mul2(A2[TRI(r, 0)], Y2[0][cp]);
#pragma unroll
                for (int k = 1; k < 8; k++)
                    d2 = fma2(A2[TRI(r, k)], Y2[k][cp], d2);
                t2[r] = d2;
            }
#pragma unroll
            for (int r = 0; r < 8; r++) {
                Y2[r][cp] = t2[r];
                Acc2[r][cp] = fma2(wi2, t2[r], Acc2[r][cp]);
            }
        }
    }

    // ---- write my half back to my smem slots (self-owned, no hazard) ----
#pragma unroll
    for (int r = 0; r < 8; r++) {
        ulonglong2 p; p.x = Acc2[r][0]; p.y = Acc2[r][1];
        *reinterpret_cast<ulonglong2*>(&s4[r * PL + tid]) = p;
    }
    __syncthreads();

    // ---- coalesced store: planar smem -> block's output chunk ----
    float4* gout = reinterpret_cast<float4*>(out) + base4;
#pragma unroll
    for (int k = 0; k < 8; k++) {
        int l4 = tid + k * TPB;
        int m = l4 >> 4, r = (l4 >> 1) & 7, q = l4 & 1;
        gout[l4] = s4[r * PL + m * 2 + q];
    }
}

extern "C" void kernel_launch(void* const* d_in, const int* in_sizes, int n_in,
                              void* d_out, int out_size) {
    const float* x = (const float*)d_in[0];
    const float* w = (const float*)d_in[1];
    float* out = (float*)d_out;
    int nmat = in_sizes[0] / 64;          // 262144
    int blocks = nmat / MPB;              // 4096 (exact)
    nslayer_kernel<<<blocks, TPB>>>(x, w, out);
}